// round 2
// baseline (speedup 1.0000x reference)
#include <cuda_runtime.h>
#include <cstdint>

#define T_MAX 512
#define B_SZ  64
#define IND   300
#define DIM   1024
#define TD    (T_MAX * DIM)      // 524288, stride of one batch row in out
#define NCTA  128
#define WST   1028               // padded smem row stride (floats)

// ---------------------------------------------------------------------------
// Device globals: grid-barrier counters (one per step) and per-batch lengths.
// ---------------------------------------------------------------------------
__device__ unsigned g_bar[T_MAX];
__device__ int      g_len[B_SZ];

// ---------------------------------------------------------------------------
// Kernel 1: lengths + barrier-counter reset (+ lengths tail of the output).
// ---------------------------------------------------------------------------
__global__ void __launch_bounds__(256) prep_kernel(const float* __restrict__ emb,
                                                   float* __restrict__ out,
                                                   int out_size) {
    int b = blockIdx.x;               // 64 blocks
    __shared__ int cnt;
    if (threadIdx.x == 0) cnt = 0;
    __syncthreads();

    int local = 0;
    for (int t = threadIdx.x; t < T_MAX; t += blockDim.x) {
        const float* p = emb + ((size_t)t * B_SZ + b) * IND;
        float s = 0.f;
        #pragma unroll 4
        for (int i = 0; i < IND; i++) s += p[i];
        if (s != 0.f) local++;
    }
    atomicAdd(&cnt, local);
    __syncthreads();

    if (threadIdx.x == 0) {
        g_len[b] = cnt;
        long long tail = (long long)T_MAX * B_SZ * DIM;
        if ((long long)out_size >= tail + B_SZ)
            out[tail + b] = (float)cnt;   // lengths appended after states
    }
    if (b == 0) {
        for (int i = threadIdx.x; i < T_MAX; i += blockDim.x) g_bar[i] = 0u;
    }
}

// ---------------------------------------------------------------------------
// Kernel 2: input projection u[t,b,:] = input_w @ emb[t,b,:] + bias,
// written directly into out[b, t, :].  M=T*B (tile=64 rows = one t), N=1024.
// ---------------------------------------------------------------------------
#define KT 32
__global__ void __launch_bounds__(256) ugemm_kernel(const float* __restrict__ emb,
                                                    const float* __restrict__ win,
                                                    const float* __restrict__ bias,
                                                    float* __restrict__ out) {
    __shared__ float As[KT][68];   // As[k][m]  (m = batch b, t fixed per CTA)
    __shared__ float Bs[KT][68];   // Bs[k][n]

    const int t  = blockIdx.x;           // 0..511
    const int n0 = blockIdx.y * 64;      // 0..960
    const int tid = threadIdx.x;
    const int tx = tid & 15, ty = tid >> 4;

    const float* arow = emb + (size_t)t * B_SZ * IND;

    float acc[4][4];
    #pragma unroll
    for (int i = 0; i < 4; i++)
        #pragma unroll
        for (int j = 0; j < 4; j++) acc[i][j] = 0.f;

    for (int kk = 0; kk < IND; kk += KT) {
        // stage A (64 x 32) and B (64 x 32), transposed into [k][row]
        #pragma unroll
        for (int s = 0; s < 2; s++) {
            int idx = tid + s * 256;       // 0..511
            int row = idx >> 3;            // 0..63
            int f4  = idx & 7;             // 0..7
            int k   = kk + f4 * 4;
            float4 va = make_float4(0.f, 0.f, 0.f, 0.f);
            float4 vb = va;
            if (k < IND) {
                va = *(const float4*)(arow + (size_t)row * IND + k);
                vb = *(const float4*)(win  + (size_t)(n0 + row) * IND + k);
            }
            As[f4 * 4 + 0][row] = va.x; As[f4 * 4 + 1][row] = va.y;
            As[f4 * 4 + 2][row] = va.z; As[f4 * 4 + 3][row] = va.w;
            Bs[f4 * 4 + 0][row] = vb.x; Bs[f4 * 4 + 1][row] = vb.y;
            Bs[f4 * 4 + 2][row] = vb.z; Bs[f4 * 4 + 3][row] = vb.w;
        }
        __syncthreads();

        #pragma unroll
        for (int k = 0; k < KT; k++) {
            float4 a = *(const float4*)&As[k][ty * 4];
            float4 b = *(const float4*)&Bs[k][tx * 4];
            acc[0][0] = fmaf(a.x, b.x, acc[0][0]); acc[0][1] = fmaf(a.x, b.y, acc[0][1]);
            acc[0][2] = fmaf(a.x, b.z, acc[0][2]); acc[0][3] = fmaf(a.x, b.w, acc[0][3]);
            acc[1][0] = fmaf(a.y, b.x, acc[1][0]); acc[1][1] = fmaf(a.y, b.y, acc[1][1]);
            acc[1][2] = fmaf(a.y, b.z, acc[1][2]); acc[1][3] = fmaf(a.y, b.w, acc[1][3]);
            acc[2][0] = fmaf(a.z, b.x, acc[2][0]); acc[2][1] = fmaf(a.z, b.y, acc[2][1]);
            acc[2][2] = fmaf(a.z, b.z, acc[2][2]); acc[2][3] = fmaf(a.z, b.w, acc[2][3]);
            acc[3][0] = fmaf(a.w, b.x, acc[3][0]); acc[3][1] = fmaf(a.w, b.y, acc[3][1]);
            acc[3][2] = fmaf(a.w, b.z, acc[3][2]); acc[3][3] = fmaf(a.w, b.w, acc[3][3]);
        }
        __syncthreads();
    }

    // epilogue: out[b, t, n] = acc + bias[n]
    const int n = n0 + tx * 4;
    float4 bv = *(const float4*)(bias + n);
    #pragma unroll
    for (int i = 0; i < 4; i++) {
        int b = ty * 4 + i;
        float4 v;
        v.x = acc[i][0] + bv.x; v.y = acc[i][1] + bv.y;
        v.z = acc[i][2] + bv.z; v.w = acc[i][3] + bv.w;
        *(float4*)(out + (size_t)b * TD + (size_t)t * DIM + n) = v;
    }
}

// ---------------------------------------------------------------------------
// Kernel 3: persistent recurrence. 128 CTAs = 2 batch halves x 64 d-tiles(16).
// W tile (16x1024) in smem for the whole kernel; x (32x1024) staged per step.
// Split-K x2 across thread halves, 2b x 2d register micro-tile.
// ---------------------------------------------------------------------------
__global__ void __launch_bounds__(256) rec_kernel(const float* __restrict__ lw,
                                                  const float* __restrict__ init,
                                                  float* __restrict__ out) {
    extern __shared__ float sm[];
    float* ws  = sm;                  // 16 * WST
    float* xs  = sm + 16 * WST;       // 32 * WST
    float* red = sm + 48 * WST;       // 512 floats

    const int c   = blockIdx.x;
    const int b0  = (c >> 6) * 32;    // batch-half base
    const int d0  = (c & 63) * 16;    // d-tile base
    const int tid = threadIdx.x;
    const int kh  = tid >> 7;         // k half: 0 or 1
    const int r   = tid & 127;
    const int tb  = r >> 3;           // 0..15  (b pair)
    const int td  = r & 7;            // 0..7   (d pair)
    const int kbase = kh * 512;

    // Stage W tile once: ws[drow][k] = layer_w[d0+drow][k]
    for (int idx = tid; idx < 16 * 256; idx += 256) {
        int drow = idx >> 8;
        int kq   = (idx & 255) * 4;
        float4 v = *(const float4*)(lw + (size_t)(d0 + drow) * DIM + kq);
        *(float4*)&ws[drow * WST + kq] = v;
    }

    const int lenA = g_len[b0 + 2 * tb];
    const int lenB = g_len[b0 + 2 * tb + 1];

    for (int t = 0; t < T_MAX; t++) {
        // ---- stage x_{t-1} into xs[32][1024] ----
        if (t == 0) {
            for (int idx = tid; idx < 32 * 256; idx += 256) {
                int brow = idx >> 8;
                int kq   = (idx & 255) * 4;
                float4 v = *(const float4*)(init + kq);
                *(float4*)&xs[brow * WST + kq] = v;
            }
        } else {
            for (int idx = tid; idx < 32 * 256; idx += 256) {
                int brow = idx >> 8;
                int kq   = (idx & 255) * 4;
                const float4* p = (const float4*)(out + (size_t)(b0 + brow) * TD
                                                      + (size_t)(t - 1) * DIM + kq);
                float4 v = __ldcg(p);
                *(float4*)&xs[brow * WST + kq] = v;
            }
        }
        __syncthreads();

        // ---- compute partial dot products over this thread's k half ----
        float a00 = 0.f, a01 = 0.f, a10 = 0.f, a11 = 0.f;
        const float* xr0 = xs + (2 * tb) * WST + kbase;
        const float* xr1 = xr0 + WST;
        const float* wr0 = ws + (2 * td) * WST + kbase;
        const float* wr1 = wr0 + WST;
        #pragma unroll 4
        for (int k = 0; k < 512; k += 4) {
            float4 xa = *(const float4*)(xr0 + k);
            float4 xb = *(const float4*)(xr1 + k);
            float4 wa = *(const float4*)(wr0 + k);
            float4 wb = *(const float4*)(wr1 + k);
            a00 = fmaf(xa.x, wa.x, a00); a00 = fmaf(xa.y, wa.y, a00);
            a00 = fmaf(xa.z, wa.z, a00); a00 = fmaf(xa.w, wa.w, a00);
            a01 = fmaf(xa.x, wb.x, a01); a01 = fmaf(xa.y, wb.y, a01);
            a01 = fmaf(xa.z, wb.z, a01); a01 = fmaf(xa.w, wb.w, a01);
            a10 = fmaf(xb.x, wa.x, a10); a10 = fmaf(xb.y, wa.y, a10);
            a10 = fmaf(xb.z, wa.z, a10); a10 = fmaf(xb.w, wa.w, a10);
            a11 = fmaf(xb.x, wb.x, a11); a11 = fmaf(xb.y, wb.y, a11);
            a11 = fmaf(xb.z, wb.z, a11); a11 = fmaf(xb.w, wb.w, a11);
        }

        if (kh == 1) {
            red[4 * r + 0] = a00; red[4 * r + 1] = a01;
            red[4 * r + 2] = a10; red[4 * r + 3] = a11;
        }
        __syncthreads();

        // ---- split-K reduce + tanh + leak + mask + store (kh==0 half) ----
        if (kh == 0) {
            float s00 = a00 + red[4 * r + 0];
            float s01 = a01 + red[4 * r + 1];
            float s10 = a10 + red[4 * r + 2];
            float s11 = a11 + red[4 * r + 3];

            const int bA = b0 + 2 * tb;
            const int d  = d0 + 2 * td;
            size_t oA = (size_t)bA * TD + (size_t)t * DIM + d;
            size_t oB = oA + (size_t)TD;

            float uA0 = out[oA], uA1 = out[oA + 1];
            float uB0 = out[oB], uB1 = out[oB + 1];
            float xoA0 = xs[(2 * tb) * WST + d];
            float xoA1 = xs[(2 * tb) * WST + d + 1];
            float xoB0 = xs[(2 * tb + 1) * WST + d];
            float xoB1 = xs[(2 * tb + 1) * WST + d + 1];

            float mA = (t < lenA) ? 1.f : 0.f;
            float mB = (t < lenB) ? 1.f : 0.f;

            out[oA]     = (0.5f * tanhf(uA0 + s00) + 0.5f * xoA0) * mA;
            out[oA + 1] = (0.5f * tanhf(uA1 + s01) + 0.5f * xoA1) * mA;
            out[oB]     = (0.5f * tanhf(uB0 + s10) + 0.5f * xoB0) * mB;
            out[oB + 1] = (0.5f * tanhf(uB1 + s11) + 0.5f * xoB1) * mB;
        }

        // ---- grid barrier (release: fence+sync+atomic; acquire: poll+fence) ----
        __threadfence();
        __syncthreads();
        if (tid == 0) {
            atomicAdd(&g_bar[t], 1u);
            while (*((volatile unsigned*)&g_bar[t]) < NCTA) { }
        }
        __syncthreads();
        __threadfence();
    }
}

// ---------------------------------------------------------------------------
// Launch
// ---------------------------------------------------------------------------
extern "C" void kernel_launch(void* const* d_in, const int* in_sizes, int n_in,
                              void* d_out, int out_size) {
    const float* emb  = (const float*)d_in[0];   // (T, B, 300)
    const float* win  = (const float*)d_in[1];   // (1024, 300)
    const float* lw   = (const float*)d_in[2];   // (1024, 1024)
    const float* bias = (const float*)d_in[3];   // (1024,)
    const float* init = (const float*)d_in[4];   // (1024,)
    float* out = (float*)d_out;                  // (B, T, 1024) states [+ lengths]

    prep_kernel<<<B_SZ, 256>>>(emb, out, out_size);

    dim3 g(T_MAX, DIM / 64);
    ugemm_kernel<<<g, 256>>>(emb, win, bias, out);

    int smem = (48 * WST + 512) * (int)sizeof(float);   // ~197.5 KB
    cudaFuncSetAttribute(rec_kernel, cudaFuncAttributeMaxDynamicSharedMemorySize, smem);
    rec_kernel<<<NCTA, 256, smem>>>(lw, init, out);
}

// round 3
// speedup vs baseline: 2.4751x; 2.4751x over previous
#include <cuda_runtime.h>
#include <cstdint>

#define T_MAX 512
#define B_SZ  64
#define IND   300
#define DIM   1024
#define TD    (T_MAX * DIM)
#define NCTA  128
#define PST   33                 // partials stride per d (pad for bank-conflict-free)
#define PROW  (16 * PST)         // 528 floats per b-row of partials

__device__ unsigned g_bar[T_MAX];
__device__ int      g_len[B_SZ];

// ---------------------------------------------------------------------------
// zero_kernel: reset barrier counters + length accumulators (also a profiling
// pad so the ncu -s 5 slot lands on rec_kernel).
// ---------------------------------------------------------------------------
__global__ void zero_kernel() {
    int i = blockIdx.x * blockDim.x + threadIdx.x;
    if (i < T_MAX) g_bar[i] = 0u;
    if (i < B_SZ)  g_len[i] = 0;
}

// ---------------------------------------------------------------------------
// prep_kernel: lengths via warp ballots + atomics. 512 CTAs = 64 b x 8 t-oct.
// ---------------------------------------------------------------------------
__global__ void __launch_bounds__(256) prep_kernel(const float* __restrict__ emb) {
    int b  = blockIdx.x & 63;
    int tq = blockIdx.x >> 6;          // 0..7
    int row = threadIdx.x >> 2;        // 0..63
    int l4  = threadIdx.x & 3;
    int t = tq * 64 + row;
    const float* p = emb + ((size_t)t * B_SZ + b) * IND;
    float s = 0.f;
    for (int i = l4; i < IND; i += 4) s += p[i];
    s += __shfl_xor_sync(~0u, s, 1);
    s += __shfl_xor_sync(~0u, s, 2);
    unsigned ball = __ballot_sync(~0u, (l4 == 0) && (s != 0.f));
    if ((threadIdx.x & 31) == 0) atomicAdd(&g_len[b], __popc(ball));
}

// ---------------------------------------------------------------------------
// tail_kernel: append lengths to the output (and act as a second pad launch).
// ---------------------------------------------------------------------------
__global__ void tail_kernel(float* __restrict__ out, int out_size) {
    int b = threadIdx.x;
    long long tail = (long long)T_MAX * B_SZ * DIM;
    if (b < B_SZ && (long long)out_size >= tail + B_SZ)
        out[tail + b] = (float)g_len[b];
}

// ---------------------------------------------------------------------------
// ugemm_kernel: u[t,b,:] = input_w @ emb[t,b,:] + bias -> out[b,t,:]
// ---------------------------------------------------------------------------
#define KT 32
__global__ void __launch_bounds__(256) ugemm_kernel(const float* __restrict__ emb,
                                                    const float* __restrict__ win,
                                                    const float* __restrict__ bias,
                                                    float* __restrict__ out) {
    __shared__ float As[KT][68];
    __shared__ float Bs[KT][68];

    const int t  = blockIdx.x;
    const int n0 = blockIdx.y * 64;
    const int tid = threadIdx.x;
    const int tx = tid & 15, ty = tid >> 4;
    const float* arow = emb + (size_t)t * B_SZ * IND;

    float acc[4][4];
    #pragma unroll
    for (int i = 0; i < 4; i++)
        #pragma unroll
        for (int j = 0; j < 4; j++) acc[i][j] = 0.f;

    for (int kk = 0; kk < IND; kk += KT) {
        #pragma unroll
        for (int s = 0; s < 2; s++) {
            int idx = tid + s * 256;
            int row = idx >> 3;
            int f4  = idx & 7;
            int k   = kk + f4 * 4;
            float4 va = make_float4(0.f, 0.f, 0.f, 0.f);
            float4 vb = va;
            if (k < IND) {
                va = *(const float4*)(arow + (size_t)row * IND + k);
                vb = *(const float4*)(win  + (size_t)(n0 + row) * IND + k);
            }
            As[f4 * 4 + 0][row] = va.x; As[f4 * 4 + 1][row] = va.y;
            As[f4 * 4 + 2][row] = va.z; As[f4 * 4 + 3][row] = va.w;
            Bs[f4 * 4 + 0][row] = vb.x; Bs[f4 * 4 + 1][row] = vb.y;
            Bs[f4 * 4 + 2][row] = vb.z; Bs[f4 * 4 + 3][row] = vb.w;
        }
        __syncthreads();

        #pragma unroll
        for (int k = 0; k < KT; k++) {
            float4 a = *(const float4*)&As[k][ty * 4];
            float4 b = *(const float4*)&Bs[k][tx * 4];
            acc[0][0] = fmaf(a.x, b.x, acc[0][0]); acc[0][1] = fmaf(a.x, b.y, acc[0][1]);
            acc[0][2] = fmaf(a.x, b.z, acc[0][2]); acc[0][3] = fmaf(a.x, b.w, acc[0][3]);
            acc[1][0] = fmaf(a.y, b.x, acc[1][0]); acc[1][1] = fmaf(a.y, b.y, acc[1][1]);
            acc[1][2] = fmaf(a.y, b.z, acc[1][2]); acc[1][3] = fmaf(a.y, b.w, acc[1][3]);
            acc[2][0] = fmaf(a.z, b.x, acc[2][0]); acc[2][1] = fmaf(a.z, b.y, acc[2][1]);
            acc[2][2] = fmaf(a.z, b.z, acc[2][2]); acc[2][3] = fmaf(a.z, b.w, acc[2][3]);
            acc[3][0] = fmaf(a.w, b.x, acc[3][0]); acc[3][1] = fmaf(a.w, b.y, acc[3][1]);
            acc[3][2] = fmaf(a.w, b.z, acc[3][2]); acc[3][3] = fmaf(a.w, b.w, acc[3][3]);
        }
        __syncthreads();
    }

    const int n = n0 + tx * 4;
    float4 bv = *(const float4*)(bias + n);
    #pragma unroll
    for (int i = 0; i < 4; i++) {
        int b = ty * 4 + i;
        float4 v;
        v.x = acc[i][0] + bv.x; v.y = acc[i][1] + bv.y;
        v.z = acc[i][2] + bv.z; v.w = acc[i][3] + bv.w;
        *(float4*)(out + (size_t)b * TD + (size_t)t * DIM + n) = v;
    }
}

// ---------------------------------------------------------------------------
// rec_kernel: persistent recurrence.
//   128 CTAs = 2 batch halves x 64 d-tiles(16).  256 threads = 32 ks x 8 td.
//   W tile lives in REGISTERS (w0/w1[32] per thread, loaded once).
//   x (32x1024) staged per step in smem with per-slice rotation swizzle.
//   Split-K x32, partials reduced through padded smem.
// ---------------------------------------------------------------------------
__device__ __forceinline__ int rot_addr(int b, int k) {
    // value x[b][k] lives at this float offset in xs
    return b * 1024 + (k & ~31) + ((((k >> 2) + (k >> 5)) & 7) << 2) + (k & 3);
}

__global__ void __launch_bounds__(256, 1) rec_kernel(const float* __restrict__ lw,
                                                     const float* __restrict__ init,
                                                     float* __restrict__ out) {
    extern __shared__ float sm[];
    float* xs = sm;                 // 32 * 1024 floats (swizzled)
    float* ps = sm + 32 * 1024;     // partials: 32 * PROW floats

    const int cta = blockIdx.x;
    const int b0  = (cta >> 6) * 32;
    const int d0  = (cta & 63) * 16;
    const int tid = threadIdx.x;
    const int ks  = tid >> 3;       // k-slice 0..31  (also this thread's output b-row)
    const int td  = tid & 7;        // d-pair 0..7    (outputs d0+2*td, d0+2*td+1)
    const int kb  = ks * 32;

    // ---- W tile into registers (once, reused for all 512 steps) ----
    float w0[32], w1[32];
    {
        const float* r0 = lw + (size_t)(d0 + 2 * td) * DIM + kb;
        const float* r1 = r0 + DIM;
        #pragma unroll
        for (int q = 0; q < 8; q++) {
            float4 a = *(const float4*)(r0 + 4 * q);
            float4 b = *(const float4*)(r1 + 4 * q);
            w0[4*q] = a.x; w0[4*q+1] = a.y; w0[4*q+2] = a.z; w0[4*q+3] = a.w;
            w1[4*q] = b.x; w1[4*q+1] = b.y; w1[4*q+2] = b.z; w1[4*q+3] = b.w;
        }
    }

    // rotated load offsets for the compute loop (slice index == ks)
    int off[8];
    #pragma unroll
    for (int q = 0; q < 8; q++) off[q] = (((q + ks) & 7) << 2);

    // staging swizzle for this thread (value quad kq = tid)
    const int st_slice = tid >> 3;
    const int st_pos   = tid & 7;
    const int st_off   = st_slice * 32 + ((((st_pos) + st_slice) & 7) << 2);

    const int len = g_len[b0 + ks];               // this thread's output b-row
    const int kx0 = d0 + 2 * td;                  // output d indices
    const int xo_a0 = rot_addr(ks, kx0);
    const int xo_a1 = rot_addr(ks, kx0 + 1);
    float* orow = out + (size_t)(b0 + ks) * TD + kx0;   // advances by DIM per step

    for (int t = 0; t < T_MAX; t++) {
        // ---- stage x_{t-1} into xs (swizzled) ----
        if (t == 0) {
            float4 v = *(const float4*)(init + tid * 4);
            #pragma unroll 4
            for (int s = 0; s < 32; s++)
                *(float4*)&xs[s * 1024 + st_off] = v;
        } else {
            const float* src = out + (size_t)b0 * TD + (size_t)(t - 1) * DIM + tid * 4;
            #pragma unroll 4
            for (int s = 0; s < 32; s++) {
                float4 v = __ldcg((const float4*)(src + (size_t)s * TD));
                *(float4*)&xs[s * 1024 + st_off] = v;
            }
        }

        // ---- prefetch u for this thread's outputs (DRAM latency hidden) ----
        float2 uv = __ldcg((const float2*)(orow + (size_t)t * DIM));

        __syncthreads();

        // ---- compute: for each b row, partial dot over this k-slice ----
        {
            const float* xr = xs + kb;
            #pragma unroll 2
            for (int b = 0; b < 32; b++) {
                float a0 = 0.f, a1 = 0.f, c0 = 0.f, c1 = 0.f;
                #pragma unroll
                for (int q = 0; q < 8; q += 2) {
                    float4 v = *(const float4*)(xr + off[q]);
                    a0 = fmaf(v.x, w0[4*q+0], a0); a1 = fmaf(v.x, w1[4*q+0], a1);
                    a0 = fmaf(v.y, w0[4*q+1], a0); a1 = fmaf(v.y, w1[4*q+1], a1);
                    a0 = fmaf(v.z, w0[4*q+2], a0); a1 = fmaf(v.z, w1[4*q+2], a1);
                    a0 = fmaf(v.w, w0[4*q+3], a0); a1 = fmaf(v.w, w1[4*q+3], a1);
                    float4 u4 = *(const float4*)(xr + off[q+1]);
                    c0 = fmaf(u4.x, w0[4*q+4], c0); c1 = fmaf(u4.x, w1[4*q+4], c1);
                    c0 = fmaf(u4.y, w0[4*q+5], c0); c1 = fmaf(u4.y, w1[4*q+5], c1);
                    c0 = fmaf(u4.z, w0[4*q+6], c0); c1 = fmaf(u4.z, w1[4*q+6], c1);
                    c0 = fmaf(u4.w, w0[4*q+7], c0); c1 = fmaf(u4.w, w1[4*q+7], c1);
                }
                ps[b * PROW + (2 * td)     * PST + ks] = a0 + c0;
                ps[b * PROW + (2 * td + 1) * PST + ks] = a1 + c1;
                xr += 1024;
            }
        }
        __syncthreads();

        // ---- split-K reduction for this thread's two outputs ----
        float s0 = 0.f, s1 = 0.f;
        {
            const float* p0 = ps + ks * PROW + (2 * td) * PST;
            const float* p1 = p0 + PST;
            #pragma unroll
            for (int i = 0; i < 32; i++) { s0 += p0[i]; s1 += p1[i]; }
        }

        // ---- epilogue: tanh + leak + mask + store ----
        {
            float xo0 = xs[xo_a0];
            float xo1 = xs[xo_a1];
            float m = (t < len) ? 1.f : 0.f;
            float y0 = (0.5f * tanhf(uv.x + s0) + 0.5f * xo0) * m;
            float y1 = (0.5f * tanhf(uv.y + s1) + 0.5f * xo1) * m;
            float2 st2; st2.x = y0; st2.y = y1;
            *(float2*)(orow + (size_t)t * DIM) = st2;
        }

        // ---- grid barrier: release arrive + acquire poll ----
        __syncthreads();
        if (tid == 0) {
            unsigned* ctr = &g_bar[t];
            asm volatile("red.release.gpu.global.add.u32 [%0], 1;" :: "l"(ctr) : "memory");
            unsigned v;
            do {
                asm volatile("ld.acquire.gpu.global.u32 %0, [%1];" : "=r"(v) : "l"(ctr) : "memory");
            } while (v < NCTA);
        }
        __syncthreads();
    }
}

// ---------------------------------------------------------------------------
// Launch: 5 kernels; with the harness's per-call extra counted launch this
// puts rec_kernel at ncu's profiled slot (-s 5).
// ---------------------------------------------------------------------------
extern "C" void kernel_launch(void* const* d_in, const int* in_sizes, int n_in,
                              void* d_out, int out_size) {
    const float* emb  = (const float*)d_in[0];   // (T, B, 300)
    const float* win  = (const float*)d_in[1];   // (1024, 300)
    const float* lw   = (const float*)d_in[2];   // (1024, 1024)
    const float* bias = (const float*)d_in[3];   // (1024,)
    const float* init = (const float*)d_in[4];   // (1024,)
    float* out = (float*)d_out;

    zero_kernel<<<2, 512>>>();
    prep_kernel<<<512, 256>>>(emb);
    tail_kernel<<<1, 64>>>(out, out_size);

    dim3 g(T_MAX, DIM / 64);
    ugemm_kernel<<<g, 256>>>(emb, win, bias, out);

    int smem = (32 * 1024 + 32 * PROW) * (int)sizeof(float);   // ~194 KB
    cudaFuncSetAttribute(rec_kernel, cudaFuncAttributeMaxDynamicSharedMemorySize, smem);
    rec_kernel<<<NCTA, 256, smem>>>(lw, init, out);
}

// round 4
// speedup vs baseline: 2.4930x; 1.0072x over previous
#include <cuda_runtime.h>
#include <cstdint>

#define T_MAX 512
#define B_SZ  64
#define IND   300
#define DIM   1024
#define TD    (T_MAX * DIM)
#define NCTA  128
#define PST   33
#define PROW  (16 * PST)

__device__ unsigned g_bar[T_MAX];
__device__ int      g_len[B_SZ];

union F2U { float2 f; unsigned long long u; };

__device__ __forceinline__ unsigned long long fma2(unsigned long long a,
                                                   unsigned long long b,
                                                   unsigned long long c) {
    unsigned long long d;
    asm("fma.rn.f32x2 %0, %1, %2, %3;" : "=l"(d) : "l"(a), "l"(b), "l"(c));
    return d;
}
__device__ __forceinline__ unsigned long long add2(unsigned long long a,
                                                   unsigned long long b) {
    unsigned long long d;
    asm("add.rn.f32x2 %0, %1, %2;" : "=l"(d) : "l"(a), "l"(b));
    return d;
}

// ---------------------------------------------------------------------------
__global__ void zero_kernel() {
    int i = blockIdx.x * blockDim.x + threadIdx.x;
    if (i < T_MAX) g_bar[i] = 0u;
    if (i < B_SZ)  g_len[i] = 0;
}

// ---------------------------------------------------------------------------
__global__ void __launch_bounds__(256) prep_kernel(const float* __restrict__ emb) {
    int b  = blockIdx.x & 63;
    int tq = blockIdx.x >> 6;
    int row = threadIdx.x >> 2;
    int l4  = threadIdx.x & 3;
    int t = tq * 64 + row;
    const float* p = emb + ((size_t)t * B_SZ + b) * IND;
    float s = 0.f;
    for (int i = l4; i < IND; i += 4) s += p[i];
    s += __shfl_xor_sync(~0u, s, 1);
    s += __shfl_xor_sync(~0u, s, 2);
    unsigned ball = __ballot_sync(~0u, (l4 == 0) && (s != 0.f));
    if ((threadIdx.x & 31) == 0) atomicAdd(&g_len[b], __popc(ball));
}

// ---------------------------------------------------------------------------
__global__ void tail_kernel(float* __restrict__ out, int out_size) {
    int b = threadIdx.x;
    long long tail = (long long)T_MAX * B_SZ * DIM;
    if (b < B_SZ && (long long)out_size >= tail + B_SZ)
        out[tail + b] = (float)g_len[b];
}

// ---------------------------------------------------------------------------
// ugemm: u[t,b,:] = input_w @ emb[t,b,:] + bias  -> out[b,t,:]
// CTA tile: 64 m (batch) x 128 n, micro 4m x 8n. 3 LDS.128 per 32 FMA.
// ---------------------------------------------------------------------------
#define KT 32
__global__ void __launch_bounds__(256) ugemm_kernel(const float* __restrict__ emb,
                                                    const float* __restrict__ win,
                                                    const float* __restrict__ bias,
                                                    float* __restrict__ out) {
    __shared__ float As[KT][68];
    __shared__ float Bs[KT][136];

    const int t  = blockIdx.x;
    const int n0 = blockIdx.y * 128;
    const int tid = threadIdx.x;
    const int tx = tid & 15, ty = tid >> 4;
    const float* arow = emb + (size_t)t * B_SZ * IND;

    float acc[4][8];
    #pragma unroll
    for (int i = 0; i < 4; i++)
        #pragma unroll
        for (int j = 0; j < 8; j++) acc[i][j] = 0.f;

    for (int kk = 0; kk < IND; kk += KT) {
        // stage A: 64 rows x 8 quads
        #pragma unroll
        for (int s = 0; s < 2; s++) {
            int idx = tid + s * 256;
            int row = idx >> 3;
            int f4  = idx & 7;
            int k   = kk + f4 * 4;
            float4 va = make_float4(0.f, 0.f, 0.f, 0.f);
            if (k < IND) va = *(const float4*)(arow + (size_t)row * IND + k);
            As[f4 * 4 + 0][row] = va.x; As[f4 * 4 + 1][row] = va.y;
            As[f4 * 4 + 2][row] = va.z; As[f4 * 4 + 3][row] = va.w;
        }
        // stage B: 128 rows x 8 quads
        #pragma unroll
        for (int s = 0; s < 4; s++) {
            int idx = tid + s * 256;
            int row = idx >> 3;
            int f4  = idx & 7;
            int k   = kk + f4 * 4;
            float4 vb = make_float4(0.f, 0.f, 0.f, 0.f);
            if (k < IND) vb = *(const float4*)(win + (size_t)(n0 + row) * IND + k);
            Bs[f4 * 4 + 0][row] = vb.x; Bs[f4 * 4 + 1][row] = vb.y;
            Bs[f4 * 4 + 2][row] = vb.z; Bs[f4 * 4 + 3][row] = vb.w;
        }
        __syncthreads();

        #pragma unroll
        for (int k = 0; k < KT; k++) {
            float4 a  = *(const float4*)&As[k][ty * 4];
            float4 b0 = *(const float4*)&Bs[k][tx * 8];
            float4 b1 = *(const float4*)&Bs[k][tx * 8 + 4];
            float av[4] = {a.x, a.y, a.z, a.w};
            float bv[8] = {b0.x, b0.y, b0.z, b0.w, b1.x, b1.y, b1.z, b1.w};
            #pragma unroll
            for (int i = 0; i < 4; i++)
                #pragma unroll
                for (int j = 0; j < 8; j++)
                    acc[i][j] = fmaf(av[i], bv[j], acc[i][j]);
        }
        __syncthreads();
    }

    const int n = n0 + tx * 8;
    float4 bv0 = *(const float4*)(bias + n);
    float4 bv1 = *(const float4*)(bias + n + 4);
    #pragma unroll
    for (int i = 0; i < 4; i++) {
        int b = ty * 4 + i;
        float4 v0, v1;
        v0.x = acc[i][0] + bv0.x; v0.y = acc[i][1] + bv0.y;
        v0.z = acc[i][2] + bv0.z; v0.w = acc[i][3] + bv0.w;
        v1.x = acc[i][4] + bv1.x; v1.y = acc[i][5] + bv1.y;
        v1.z = acc[i][6] + bv1.z; v1.w = acc[i][7] + bv1.w;
        *(float4*)(out + (size_t)b * TD + (size_t)t * DIM + n)     = v0;
        *(float4*)(out + (size_t)b * TD + (size_t)t * DIM + n + 4) = v1;
    }
}

// ---------------------------------------------------------------------------
// rec_kernel: persistent recurrence with packed f32x2 FMAs.
//   128 CTAs = 2 batch halves x 64 d-tiles(16). 256 threads = 32 ks x 8 td.
//   W in registers as f32x2 pairs; lane0 = even-k sum, lane1 = odd-k sum.
// ---------------------------------------------------------------------------
__device__ __forceinline__ int rot_addr(int b, int k) {
    return b * 1024 + (k & ~31) + ((((k >> 2) + (k >> 5)) & 7) << 2) + (k & 3);
}

__global__ void __launch_bounds__(256, 1) rec_kernel(const float* __restrict__ lw,
                                                     const float* __restrict__ init,
                                                     float* __restrict__ out) {
    extern __shared__ float sm[];
    float* xs = sm;                 // 32 * 1024 floats (swizzled)
    float* ps = sm + 32 * 1024;     // partials

    const int cta = blockIdx.x;
    const int b0  = (cta >> 6) * 32;
    const int d0  = (cta & 63) * 16;
    const int tid = threadIdx.x;
    const int ks  = tid >> 3;
    const int td  = tid & 7;
    const int kb  = ks * 32;

    // W tile into registers as f32x2 pairs
    unsigned long long w0p[16], w1p[16];
    {
        const float* r0 = lw + (size_t)(d0 + 2 * td) * DIM + kb;
        const float* r1 = r0 + DIM;
        #pragma unroll
        for (int q = 0; q < 8; q++) {
            float4 a = *(const float4*)(r0 + 4 * q);
            float4 b = *(const float4*)(r1 + 4 * q);
            F2U t0, t1, t2, t3;
            t0.f = make_float2(a.x, a.y); t1.f = make_float2(a.z, a.w);
            t2.f = make_float2(b.x, b.y); t3.f = make_float2(b.z, b.w);
            w0p[2 * q] = t0.u; w0p[2 * q + 1] = t1.u;
            w1p[2 * q] = t2.u; w1p[2 * q + 1] = t3.u;
        }
    }

    int off[8];
    #pragma unroll
    for (int q = 0; q < 8; q++) off[q] = (((q + ks) & 7) << 2);

    const int st_slice = tid >> 3;
    const int st_pos   = tid & 7;
    const int st_off   = st_slice * 32 + (((st_pos + st_slice) & 7) << 2);

    const int len = g_len[b0 + ks];
    const int kx0 = d0 + 2 * td;
    const int xo_a0 = rot_addr(ks, kx0);
    const int xo_a1 = rot_addr(ks, kx0 + 1);
    float* orow = out + (size_t)(b0 + ks) * TD + kx0;

    for (int t = 0; t < T_MAX; t++) {
        // ---- stage x_{t-1} into xs (swizzled) ----
        if (t == 0) {
            float4 v = *(const float4*)(init + tid * 4);
            #pragma unroll 4
            for (int s = 0; s < 32; s++)
                *(float4*)&xs[s * 1024 + st_off] = v;
        } else {
            const float* src = out + (size_t)b0 * TD + (size_t)(t - 1) * DIM + tid * 4;
            #pragma unroll 4
            for (int s = 0; s < 32; s++) {
                float4 v = __ldcg((const float4*)(src + (size_t)s * TD));
                *(float4*)&xs[s * 1024 + st_off] = v;
            }
        }

        float2 uv = __ldcg((const float2*)(orow + (size_t)t * DIM));

        __syncthreads();

        // ---- compute partial dots with packed f32x2 ----
        {
            const float* xr = xs + kb;
            #pragma unroll 2
            for (int b = 0; b < 32; b++) {
                unsigned long long a0a = 0ull, a0b = 0ull, a1a = 0ull, a1b = 0ull;
                #pragma unroll
                for (int q = 0; q < 8; q++) {
                    ulonglong2 v = *(const ulonglong2*)(xr + off[q]);
                    a0a = fma2(v.x, w0p[2 * q],     a0a);
                    a0b = fma2(v.y, w0p[2 * q + 1], a0b);
                    a1a = fma2(v.x, w1p[2 * q],     a1a);
                    a1b = fma2(v.y, w1p[2 * q + 1], a1b);
                }
                F2U s0, s1;
                s0.u = add2(a0a, a0b);
                s1.u = add2(a1a, a1b);
                ps[b * PROW + (2 * td)     * PST + ks] = s0.f.x + s0.f.y;
                ps[b * PROW + (2 * td + 1) * PST + ks] = s1.f.x + s1.f.y;
                xr += 1024;
            }
        }
        __syncthreads();

        // ---- split-K reduction ----
        float s0 = 0.f, s1 = 0.f;
        {
            const float* p0 = ps + ks * PROW + (2 * td) * PST;
            const float* p1 = p0 + PST;
            #pragma unroll
            for (int i = 0; i < 32; i++) { s0 += p0[i]; s1 += p1[i]; }
        }

        // ---- epilogue ----
        {
            float xo0 = xs[xo_a0];
            float xo1 = xs[xo_a1];
            float m = (t < len) ? 1.f : 0.f;
            float y0 = (0.5f * tanhf(uv.x + s0) + 0.5f * xo0) * m;
            float y1 = (0.5f * tanhf(uv.y + s1) + 0.5f * xo1) * m;
            float2 st2; st2.x = y0; st2.y = y1;
            *(float2*)(orow + (size_t)t * DIM) = st2;
        }

        // ---- grid barrier ----
        __syncthreads();
        if (tid == 0) {
            unsigned* ctr = &g_bar[t];
            asm volatile("red.release.gpu.global.add.u32 [%0], 1;" :: "l"(ctr) : "memory");
            unsigned v;
            do {
                asm volatile("ld.acquire.gpu.global.u32 %0, [%1];" : "=r"(v) : "l"(ctr) : "memory");
            } while (v < NCTA);
        }
        __syncthreads();
    }
}

// ---------------------------------------------------------------------------
extern "C" void kernel_launch(void* const* d_in, const int* in_sizes, int n_in,
                              void* d_out, int out_size) {
    const float* emb  = (const float*)d_in[0];
    const float* win  = (const float*)d_in[1];
    const float* lw   = (const float*)d_in[2];
    const float* bias = (const float*)d_in[3];
    const float* init = (const float*)d_in[4];
    float* out = (float*)d_out;

    zero_kernel<<<2, 512>>>();
    prep_kernel<<<512, 256>>>(emb);

    dim3 g(T_MAX, DIM / 128);
    ugemm_kernel<<<g, 256>>>(emb, win, bias, out);

    int smem = (32 * 1024 + 32 * PROW) * (int)sizeof(float);
    cudaFuncSetAttribute(rec_kernel, cudaFuncAttributeMaxDynamicSharedMemorySize, smem);
    rec_kernel<<<NCTA, 256, smem>>>(lw, init, out);

    tail_kernel<<<1, 64>>>(out, out_size);
}

// round 5
// speedup vs baseline: 3.2450x; 1.3017x over previous
#include <cuda_runtime.h>
#include <cstdint>

#define T_MAX 512
#define B_SZ  64
#define IND   300
#define DIM   1024
#define TD    (T_MAX * DIM)
#define NCTA  128
#define HALF_CTAS 64
#define PST   33
#define PROW  (16 * PST)

__device__ unsigned g_bar[2 * T_MAX];
__device__ int      g_len[B_SZ];

union F2U { float2 f; unsigned long long u; };

__device__ __forceinline__ unsigned long long fma2(unsigned long long a,
                                                   unsigned long long b,
                                                   unsigned long long c) {
    unsigned long long d;
    asm("fma.rn.f32x2 %0, %1, %2, %3;" : "=l"(d) : "l"(a), "l"(b), "l"(c));
    return d;
}
__device__ __forceinline__ unsigned long long add2(unsigned long long a,
                                                   unsigned long long b) {
    unsigned long long d;
    asm("add.rn.f32x2 %0, %1, %2;" : "=l"(d) : "l"(a), "l"(b));
    return d;
}

// ---------------------------------------------------------------------------
__global__ void zero_kernel() {
    int i = blockIdx.x * blockDim.x + threadIdx.x;
    if (i < 2 * T_MAX) g_bar[i] = 0u;
    if (i < B_SZ)      g_len[i] = 0;
}

// ---------------------------------------------------------------------------
__global__ void __launch_bounds__(256) prep_kernel(const float* __restrict__ emb) {
    int b  = blockIdx.x & 63;
    int tq = blockIdx.x >> 6;
    int row = threadIdx.x >> 2;
    int l4  = threadIdx.x & 3;
    int t = tq * 64 + row;
    const float* p = emb + ((size_t)t * B_SZ + b) * IND;
    float s = 0.f;
    for (int i = l4; i < IND; i += 4) s += p[i];
    s += __shfl_xor_sync(~0u, s, 1);
    s += __shfl_xor_sync(~0u, s, 2);
    unsigned ball = __ballot_sync(~0u, (l4 == 0) && (s != 0.f));
    if ((threadIdx.x & 31) == 0) atomicAdd(&g_len[b], __popc(ball));
}

// ---------------------------------------------------------------------------
__global__ void tail_kernel(float* __restrict__ out, int out_size) {
    int b = threadIdx.x;
    long long tail = (long long)T_MAX * B_SZ * DIM;
    if (b < B_SZ && (long long)out_size >= tail + B_SZ)
        out[tail + b] = (float)g_len[b];
}

// ---------------------------------------------------------------------------
// ugemm: u[t,b,:] = input_w @ emb[t,b,:] + bias -> out[b,t,:]
// ---------------------------------------------------------------------------
#define KT 32
__global__ void __launch_bounds__(256) ugemm_kernel(const float* __restrict__ emb,
                                                    const float* __restrict__ win,
                                                    const float* __restrict__ bias,
                                                    float* __restrict__ out) {
    __shared__ float As[KT][68];
    __shared__ float Bs[KT][136];

    const int t  = blockIdx.x;
    const int n0 = blockIdx.y * 128;
    const int tid = threadIdx.x;
    const int tx = tid & 15, ty = tid >> 4;
    const float* arow = emb + (size_t)t * B_SZ * IND;

    float acc[4][8];
    #pragma unroll
    for (int i = 0; i < 4; i++)
        #pragma unroll
        for (int j = 0; j < 8; j++) acc[i][j] = 0.f;

    for (int kk = 0; kk < IND; kk += KT) {
        #pragma unroll
        for (int s = 0; s < 2; s++) {
            int idx = tid + s * 256;
            int row = idx >> 3;
            int f4  = idx & 7;
            int k   = kk + f4 * 4;
            float4 va = make_float4(0.f, 0.f, 0.f, 0.f);
            if (k < IND) va = *(const float4*)(arow + (size_t)row * IND + k);
            As[f4 * 4 + 0][row] = va.x; As[f4 * 4 + 1][row] = va.y;
            As[f4 * 4 + 2][row] = va.z; As[f4 * 4 + 3][row] = va.w;
        }
        #pragma unroll
        for (int s = 0; s < 4; s++) {
            int idx = tid + s * 256;
            int row = idx >> 3;
            int f4  = idx & 7;
            int k   = kk + f4 * 4;
            float4 vb = make_float4(0.f, 0.f, 0.f, 0.f);
            if (k < IND) vb = *(const float4*)(win + (size_t)(n0 + row) * IND + k);
            Bs[f4 * 4 + 0][row] = vb.x; Bs[f4 * 4 + 1][row] = vb.y;
            Bs[f4 * 4 + 2][row] = vb.z; Bs[f4 * 4 + 3][row] = vb.w;
        }
        __syncthreads();

        #pragma unroll
        for (int k = 0; k < KT; k++) {
            float4 a  = *(const float4*)&As[k][ty * 4];
            float4 b0 = *(const float4*)&Bs[k][tx * 8];
            float4 b1 = *(const float4*)&Bs[k][tx * 8 + 4];
            float av[4] = {a.x, a.y, a.z, a.w};
            float bv[8] = {b0.x, b0.y, b0.z, b0.w, b1.x, b1.y, b1.z, b1.w};
            #pragma unroll
            for (int i = 0; i < 4; i++)
                #pragma unroll
                for (int j = 0; j < 8; j++)
                    acc[i][j] = fmaf(av[i], bv[j], acc[i][j]);
        }
        __syncthreads();
    }

    const int n = n0 + tx * 8;
    float4 bv0 = *(const float4*)(bias + n);
    float4 bv1 = *(const float4*)(bias + n + 4);
    #pragma unroll
    for (int i = 0; i < 4; i++) {
        int b = ty * 4 + i;
        float4 v0, v1;
        v0.x = acc[i][0] + bv0.x; v0.y = acc[i][1] + bv0.y;
        v0.z = acc[i][2] + bv0.z; v0.w = acc[i][3] + bv0.w;
        v1.x = acc[i][4] + bv1.x; v1.y = acc[i][5] + bv1.y;
        v1.z = acc[i][6] + bv1.z; v1.w = acc[i][7] + bv1.w;
        *(float4*)(out + (size_t)b * TD + (size_t)t * DIM + n)     = v0;
        *(float4*)(out + (size_t)b * TD + (size_t)t * DIM + n + 4) = v1;
    }
}

// ---------------------------------------------------------------------------
// rec_kernel: persistent recurrence.
//   128 CTAs = 2 independent batch halves x 64 d-tiles(16).
//   cp.async staging in 4 groups, pipelined into the compute b-loop.
//   Per-half grid barriers (relaxed poll + acquire on exit).
// ---------------------------------------------------------------------------
__device__ __forceinline__ int rot_addr(int b, int k) {
    return b * 1024 + (k & ~31) + ((((k >> 2) + (k >> 5)) & 7) << 2) + (k & 3);
}

__global__ void __launch_bounds__(256, 1) rec_kernel(const float* __restrict__ lw,
                                                     const float* __restrict__ init,
                                                     float* __restrict__ out) {
    extern __shared__ float sm[];
    float* xs = sm;                 // 32 * 1024 floats (swizzled)
    float* ps = sm + 32 * 1024;     // partials

    const int cta  = blockIdx.x;
    const int half = cta >> 6;
    const int b0   = half * 32;
    const int d0   = (cta & 63) * 16;
    const int tid  = threadIdx.x;
    const int ks   = tid >> 3;
    const int td   = tid & 7;
    const int kb   = ks * 32;

    // W tile into registers as f32x2 pairs
    unsigned long long w0p[16], w1p[16];
    {
        const float* r0 = lw + (size_t)(d0 + 2 * td) * DIM + kb;
        const float* r1 = r0 + DIM;
        #pragma unroll
        for (int q = 0; q < 8; q++) {
            float4 a = *(const float4*)(r0 + 4 * q);
            float4 b = *(const float4*)(r1 + 4 * q);
            F2U t0, t1, t2, t3;
            t0.f = make_float2(a.x, a.y); t1.f = make_float2(a.z, a.w);
            t2.f = make_float2(b.x, b.y); t3.f = make_float2(b.z, b.w);
            w0p[2 * q] = t0.u; w0p[2 * q + 1] = t1.u;
            w1p[2 * q] = t2.u; w1p[2 * q + 1] = t3.u;
        }
    }

    int off[8];
    #pragma unroll
    for (int q = 0; q < 8; q++) off[q] = (((q + ks) & 7) << 2);

    const int st_slice = tid >> 3;
    const int st_pos   = tid & 7;
    const int st_off   = st_slice * 32 + (((st_pos + st_slice) & 7) << 2);
    const unsigned xs_u32 = (unsigned)__cvta_generic_to_shared(xs) + (unsigned)(st_off * 4);

    const int len = g_len[b0 + ks];
    const int kx0 = d0 + 2 * td;
    const int xo_a0 = rot_addr(ks, kx0);
    const int xo_a1 = rot_addr(ks, kx0 + 1);
    float* orow = out + (size_t)(b0 + ks) * TD + kx0;
    unsigned* ctr_base = &g_bar[half * T_MAX];

    for (int t = 0; t < T_MAX; t++) {
        // ---- u prefetch first (independent of other CTAs' stores) ----
        float2 uv = __ldcg((const float2*)(orow + (size_t)t * DIM));

        // ---- stage x_{t-1} ----
        if (t == 0) {
            float4 v = *(const float4*)(init + tid * 4);
            #pragma unroll 4
            for (int s = 0; s < 32; s++)
                *(float4*)&xs[s * 1024 + st_off] = v;
            __syncthreads();
        } else {
            const float* src = out + (size_t)b0 * TD + (size_t)(t - 1) * DIM + tid * 4;
            #pragma unroll
            for (int s = 0; s < 32; s++) {
                asm volatile("cp.async.cg.shared.global [%0], [%1], 16;"
                             :: "r"(xs_u32 + (unsigned)(s * 4096)),
                                "l"(src + (size_t)s * TD) : "memory");
                if ((s & 7) == 7) asm volatile("cp.async.commit_group;" ::: "memory");
            }
        }

        // ---- compute, consuming staged chunks in order ----
        #pragma unroll
        for (int c = 0; c < 4; c++) {
            if (t != 0) {
                if      (c == 0) asm volatile("cp.async.wait_group 3;" ::: "memory");
                else if (c == 1) asm volatile("cp.async.wait_group 2;" ::: "memory");
                else if (c == 2) asm volatile("cp.async.wait_group 1;" ::: "memory");
                else             asm volatile("cp.async.wait_group 0;" ::: "memory");
                __syncthreads();
            }
            const float* xr = xs + (size_t)(c * 8) * 1024 + kb;
            #pragma unroll
            for (int bb = 0; bb < 8; bb++) {
                int b = c * 8 + bb;
                unsigned long long a0a = 0ull, a0b = 0ull, a1a = 0ull, a1b = 0ull;
                #pragma unroll
                for (int q = 0; q < 8; q++) {
                    ulonglong2 v = *(const ulonglong2*)(xr + off[q]);
                    a0a = fma2(v.x, w0p[2 * q],     a0a);
                    a0b = fma2(v.y, w0p[2 * q + 1], a0b);
                    a1a = fma2(v.x, w1p[2 * q],     a1a);
                    a1b = fma2(v.y, w1p[2 * q + 1], a1b);
                }
                F2U s0, s1;
                s0.u = add2(a0a, a0b);
                s1.u = add2(a1a, a1b);
                ps[b * PROW + (2 * td)     * PST + ks] = s0.f.x + s0.f.y;
                ps[b * PROW + (2 * td + 1) * PST + ks] = s1.f.x + s1.f.y;
                xr += 1024;
            }
        }
        __syncthreads();

        // ---- split-K reduction ----
        float s0 = 0.f, s1 = 0.f;
        {
            const float* p0 = ps + ks * PROW + (2 * td) * PST;
            const float* p1 = p0 + PST;
            #pragma unroll
            for (int i = 0; i < 32; i++) { s0 += p0[i]; s1 += p1[i]; }
        }

        // ---- epilogue ----
        {
            float xo0 = xs[xo_a0];
            float xo1 = xs[xo_a1];
            float m = (t < len) ? 1.f : 0.f;
            float y0 = (0.5f * tanhf(uv.x + s0) + 0.5f * xo0) * m;
            float y1 = (0.5f * tanhf(uv.y + s1) + 0.5f * xo1) * m;
            float2 st2; st2.x = y0; st2.y = y1;
            *(float2*)(orow + (size_t)t * DIM) = st2;
        }

        // ---- per-half grid barrier ----
        __syncthreads();
        if (tid == 0) {
            unsigned* ctr = ctr_base + t;
            asm volatile("red.release.gpu.global.add.u32 [%0], 1;" :: "l"(ctr) : "memory");
            unsigned v;
            do {
                asm volatile("ld.relaxed.gpu.global.u32 %0, [%1];" : "=r"(v) : "l"(ctr) : "memory");
            } while (v < HALF_CTAS);
            asm volatile("ld.acquire.gpu.global.u32 %0, [%1];" : "=r"(v) : "l"(ctr) : "memory");
        }
        __syncthreads();
    }
}

// ---------------------------------------------------------------------------
extern "C" void kernel_launch(void* const* d_in, const int* in_sizes, int n_in,
                              void* d_out, int out_size) {
    const float* emb  = (const float*)d_in[0];
    const float* win  = (const float*)d_in[1];
    const float* lw   = (const float*)d_in[2];
    const float* bias = (const float*)d_in[3];
    const float* init = (const float*)d_in[4];
    float* out = (float*)d_out;

    zero_kernel<<<2, 512>>>();
    prep_kernel<<<512, 256>>>(emb);

    dim3 g(T_MAX, DIM / 128);
    ugemm_kernel<<<g, 256>>>(emb, win, bias, out);

    int smem = (32 * 1024 + 32 * PROW) * (int)sizeof(float);
    cudaFuncSetAttribute(rec_kernel, cudaFuncAttributeMaxDynamicSharedMemorySize, smem);
    rec_kernel<<<NCTA, 256, smem>>>(lw, init, out);

    tail_kernel<<<1, 64>>>(out, out_size);
}